// round 1
// baseline (speedup 1.0000x reference)
#include <cuda_runtime.h>
#include <math.h>

// ---------------- sizes ----------------
#define BATCH 16
#define H0 256
#define W0 256
#define CIN 3
#define HID 128
#define EMB 64
#define KCODES 1024
#define H1v 128
#define W1v 128
#define H2v 64
#define W2v 64

#define XREC_ELEMS (BATCH*H0*W0*3)      // 3145728
#define TOK_OFF    XREC_ELEMS
#define TOK_ELEMS  (BATCH*H2v*W2v)      // 65536
#define LOSS_OFF   (TOK_OFF + TOK_ELEMS)

// ---------------- scratch ----------------
__device__ float g_h1[BATCH*H1v*W1v*HID];   // encoder conv1 out (gelu'd)
__device__ float g_ze[BATCH*H2v*W2v*EMB];   // z_e
__device__ float g_zst[BATCH*H2v*W2v*EMB];  // z_st
__device__ float g_g1[BATCH*H1v*W1v*HID];   // decoder convt1 out (gelu'd)
__device__ float g_loss;

__device__ __forceinline__ float gelu_f(float x) {
    float t = 0.7978845608028654f * (x + 0.044715f * x * x * x);
    return 0.5f * x * (1.0f + tanhf(t));
}

// ================= conv1: x[16,256,256,3] -> h1[16,128,128,128], 4x4 s2 SAME, gelu =================
// block = 128 threads (one per co), tile = 16 output x positions. grid (8,128,16)
__global__ void k_conv1(const float* __restrict__ x, const float* __restrict__ w,
                        const float* __restrict__ b) {
    __shared__ float ws[4*4*3*128];   // 24 KB
    __shared__ float ins[4*34*3];     // input tile
    int tid = threadIdx.x;
    int bx = blockIdx.x, oy = blockIdx.y, n = blockIdx.z;
    if (bx == 0 && oy == 0 && n == 0 && tid == 0) g_loss = 0.0f;
    for (int i = tid; i < 6144; i += 128) ws[i] = w[i];
    int x0 = bx * 16;
    for (int i = tid; i < 4*34*3; i += 128) {
        int r = i / (34*3); int rem = i - r*(34*3); int c = rem / 3; int ch = rem % 3;
        int gy = 2*oy - 1 + r;
        int gx = 2*x0 - 1 + c;
        float v = 0.0f;
        if (gy >= 0 && gy < H0 && gx >= 0 && gx < W0) v = x[((n*H0+gy)*W0+gx)*CIN + ch];
        ins[i] = v;
    }
    __syncthreads();
    int co = tid;
    float bias = b[co];
    float acc[16];
#pragma unroll
    for (int p = 0; p < 16; p++) acc[p] = bias;
    for (int ky = 0; ky < 4; ky++) {
        for (int kx = 0; kx < 4; kx++) {
#pragma unroll
            for (int ci = 0; ci < 3; ci++) {
                float wv = ws[((ky*4+kx)*3+ci)*128 + co];
#pragma unroll
                for (int p = 0; p < 16; p++) {
                    acc[p] = fmaf(ins[(ky*34 + 2*p + kx)*3 + ci], wv, acc[p]);
                }
            }
        }
    }
#pragma unroll
    for (int p = 0; p < 16; p++) {
        g_h1[((n*H1v+oy)*W1v + x0 + p)*HID + co] = gelu_f(acc[p]);
    }
}

// ================= conv2 + gelu + 1x1 proj: h1 -> z_e[16,64,64,64] =================
// block = 256 threads, tile = 16 output pixels x 128 co.  grid (4,64,16). dyn smem.
#define CS2 130
#define INS2 (4*34*CS2)
__global__ void k_conv2(const float* __restrict__ w2, const float* __restrict__ b2,
                        const float* __restrict__ w3, const float* __restrict__ b3) {
    extern __shared__ float sm[];
    float* ins = sm;             // [4 rows][34 cols][ci] stride CS2
    float* h2s = sm + INS2;      // [16 px][132]
    int tid = threadIdx.x;
    int bx = blockIdx.x, oy = blockIdx.y, n = blockIdx.z;
    int x0 = bx * 16;
    // stage input tile via float2 (scalar smem stores to keep odd-ish stride)
    for (int i = tid; i < 4*34*64; i += 256) {
        int r = i / (34*64); int rem = i - r*(34*64); int c = rem / 64; int h = rem - c*64;
        int gy = 2*oy - 1 + r;
        int gx = 2*x0 - 1 + c;
        float2 v = make_float2(0.0f, 0.0f);
        if (gy >= 0 && gy < H1v && gx >= 0 && gx < W1v)
            v = *reinterpret_cast<const float2*>(&g_h1[((n*H1v+gy)*W1v+gx)*HID + 2*h]);
        float* dst = &ins[(r*34+c)*CS2 + 2*h];
        dst[0] = v.x; dst[1] = v.y;
    }
    __syncthreads();
    int p = tid & 15;
    int co = (tid >> 4) * 8;
    float acc[8];
    {
        float4 b0 = *reinterpret_cast<const float4*>(&b2[co]);
        float4 b1 = *reinterpret_cast<const float4*>(&b2[co+4]);
        acc[0]=b0.x; acc[1]=b0.y; acc[2]=b0.z; acc[3]=b0.w;
        acc[4]=b1.x; acc[5]=b1.y; acc[6]=b1.z; acc[7]=b1.w;
    }
    for (int ky = 0; ky < 4; ky++) {
        for (int kx = 0; kx < 4; kx++) {
            const float* inrow = &ins[(ky*34 + 2*p + kx)*CS2];
            const float* wrow  = &w2[((ky*4+kx)*128)*128 + co];
#pragma unroll 4
            for (int ci = 0; ci < 128; ci++) {
                float a = inrow[ci];
                float4 w0 = *reinterpret_cast<const float4*>(wrow + ci*128);
                float4 w1 = *reinterpret_cast<const float4*>(wrow + ci*128 + 4);
                acc[0]=fmaf(a,w0.x,acc[0]); acc[1]=fmaf(a,w0.y,acc[1]);
                acc[2]=fmaf(a,w0.z,acc[2]); acc[3]=fmaf(a,w0.w,acc[3]);
                acc[4]=fmaf(a,w1.x,acc[4]); acc[5]=fmaf(a,w1.y,acc[5]);
                acc[6]=fmaf(a,w1.z,acc[6]); acc[7]=fmaf(a,w1.w,acc[7]);
            }
        }
    }
    // gelu -> stash h2 tile in smem
    {
        float4 o0, o1;
        o0.x=gelu_f(acc[0]); o0.y=gelu_f(acc[1]); o0.z=gelu_f(acc[2]); o0.w=gelu_f(acc[3]);
        o1.x=gelu_f(acc[4]); o1.y=gelu_f(acc[5]); o1.z=gelu_f(acc[6]); o1.w=gelu_f(acc[7]);
        *reinterpret_cast<float4*>(&h2s[p*132 + co])     = o0;
        *reinterpret_cast<float4*>(&h2s[p*132 + co + 4]) = o1;
    }
    __syncthreads();
    // fused 1x1: z_e[px][e4..e4+3]
    int px = tid & 15;
    int e  = (tid >> 4) * 4;
    float4 bb = *reinterpret_cast<const float4*>(&b3[e]);
    float z0=bb.x, z1=bb.y, z2=bb.z, z3=bb.w;
#pragma unroll 4
    for (int ci = 0; ci < 128; ci++) {
        float hv = h2s[px*132 + ci];
        float4 wv = *reinterpret_cast<const float4*>(&w3[ci*EMB + e]);
        z0 = fmaf(hv, wv.x, z0); z1 = fmaf(hv, wv.y, z1);
        z2 = fmaf(hv, wv.z, z2); z3 = fmaf(hv, wv.w, z3);
    }
    float4 out = make_float4(z0, z1, z2, z3);
    *reinterpret_cast<float4*>(&g_ze[((n*H2v+oy)*W2v + x0 + px)*EMB + e]) = out;
}

// ================= VQ: argmin over 1024 codes, tok + z_st + loss =================
// block = 128 threads, 16 pixels per block. grid 4096.
#define CSTR 68
__global__ void k_vq(const float* __restrict__ cb, float* __restrict__ dout) {
    __shared__ float cs[64*CSTR];
    __shared__ float e2s[64];
    __shared__ float bval[128];
    __shared__ int   bidx[128];
    __shared__ int   widx[16];
    __shared__ float lred[128];
    int tid = threadIdx.x;
    int pb = blockIdx.x * 16;
    int p = tid & 15;
    int g = tid >> 4;   // 0..7
    float4 z4[16];
    const float* zp = &g_ze[(pb + p)*EMB];
#pragma unroll
    for (int i = 0; i < 16; i++) z4[i] = *reinterpret_cast<const float4*>(&zp[4*i]);
    float best = 3.4e38f; int bi = 0;
    for (int ch = 0; ch < 16; ch++) {
        for (int i = tid; i < 64*16; i += 128) {
            int cj = i >> 4; int d4 = i & 15;
            float4 v = *reinterpret_cast<const float4*>(&cb[(ch*64+cj)*EMB + 4*d4]);
            *reinterpret_cast<float4*>(&cs[cj*CSTR + 4*d4]) = v;
        }
        __syncthreads();
        if (tid < 64) {
            float s = 0.0f;
#pragma unroll 8
            for (int d = 0; d < 64; d++) { float c = cs[tid*CSTR + d]; s = fmaf(c, c, s); }
            e2s[tid] = s;
        }
        __syncthreads();
#pragma unroll
        for (int j = 0; j < 8; j++) {
            int cj = g*8 + j;
            const float* cp = &cs[cj*CSTR];
            float dot = 0.0f;
#pragma unroll
            for (int i = 0; i < 16; i++) {
                float4 c = *reinterpret_cast<const float4*>(&cp[4*i]);
                dot = fmaf(z4[i].x, c.x, dot); dot = fmaf(z4[i].y, c.y, dot);
                dot = fmaf(z4[i].z, c.z, dot); dot = fmaf(z4[i].w, c.w, dot);
            }
            float dist = e2s[cj] - 2.0f*dot;
            int gidx = ch*64 + cj;
            if (dist < best || (dist == best && gidx < bi)) { best = dist; bi = gidx; }
        }
        __syncthreads();
    }
    bval[tid] = best; bidx[tid] = bi;
    __syncthreads();
    if (tid < 16) {
        float bb = bval[tid]; int bbi = bidx[tid];
        for (int k = 1; k < 8; k++) {
            float v = bval[tid + 16*k]; int vi = bidx[tid + 16*k];
            if (v < bb || (v == bb && vi < bbi)) { bb = v; bbi = vi; }
        }
        widx[tid] = bbi;
        dout[TOK_OFF + pb + tid] = (float)bbi;
    }
    __syncthreads();
    int idx = widx[p];
    float lsum = 0.0f;
    const float* cq = &cb[idx*EMB + g*8];
    const float* ze = &g_ze[(pb + p)*EMB + g*8];
    float*       zs = &g_zst[(pb + p)*EMB + g*8];
#pragma unroll
    for (int d = 0; d < 8; d++) {
        float zq = cq[d]; float z = ze[d];
        float diff = zq - z;
        zs[d] = z + diff;        // replicate z_e + (z_q - z_e) rounding
        lsum = fmaf(diff, diff, lsum);
    }
    lred[tid] = lsum;
    __syncthreads();
    for (int s = 64; s > 0; s >>= 1) {
        if (tid < s) lred[tid] += lred[tid + s];
        __syncthreads();
    }
    if (tid == 0) atomicAdd(&g_loss, lred[0]);
}

// ================= convt1: z_st[16,64,64,64] -> g1[16,128,128,128] (gelu) =================
// block = 256 threads, tile 32 out px x 128 co. grid (4,128,16).
#define CT1 68
__global__ void k_convt1(const float* __restrict__ w, const float* __restrict__ b) {
    __shared__ float ins[2*18*CT1];
    int tid = threadIdx.x;
    int bx = blockIdx.x, oy = blockIdx.y, n = blockIdx.z;
    int x0 = bx * 32;
    int kyA = (oy & 1);
    int iy0 = (oy + kyA - 2) >> 1;  // even value, exact
    int c0 = (x0 >> 1) - 1;
    for (int i = tid; i < 2*18*16; i += 256) {
        int r = i / (18*16); int rem = i - r*(18*16); int c = rem >> 4; int d4 = rem & 15;
        int iy = iy0 + r; int ix = c0 + c;
        float4 v = make_float4(0,0,0,0);
        if (iy >= 0 && iy < H2v && ix >= 0 && ix < W2v)
            v = *reinterpret_cast<const float4*>(&g_zst[((n*H2v+iy)*W2v+ix)*EMB + 4*d4]);
        *reinterpret_cast<float4*>(&ins[(r*18+c)*CT1 + 4*d4]) = v;
    }
    __syncthreads();
    int p = tid & 15;
    int par = p >> 3;
    int q = p & 7;
    int xl = 2*q + par;            // pixels xl, xl+16 (same parity)
    int co = (tid >> 4) * 8;
    float acc[2][8];
    {
        float4 b0 = *reinterpret_cast<const float4*>(&b[co]);
        float4 b1 = *reinterpret_cast<const float4*>(&b[co+4]);
#pragma unroll
        for (int m = 0; m < 2; m++) {
            acc[m][0]=b0.x; acc[m][1]=b0.y; acc[m][2]=b0.z; acc[m][3]=b0.w;
            acc[m][4]=b1.x; acc[m][5]=b1.y; acc[m][6]=b1.z; acc[m][7]=b1.w;
        }
    }
    int kxA = par;
#pragma unroll
    for (int kyi = 0; kyi < 2; kyi++) {
        int ky = kyA + 2*kyi;
#pragma unroll
        for (int kxi = 0; kxi < 2; kxi++) {
            int kx = kxA + 2*kxi;
            int c = (xl + kx) >> 1;
            const float* i0 = &ins[(kyi*18 + c)*CT1];
            const float* i1 = i0 + 8*CT1;
            const float* wr = &w[((ky*4+kx)*EMB)*HID + co];
#pragma unroll 4
            for (int ci = 0; ci < 64; ci++) {
                float a0 = i0[ci], a1 = i1[ci];
                float4 w0 = *reinterpret_cast<const float4*>(wr + ci*HID);
                float4 w1 = *reinterpret_cast<const float4*>(wr + ci*HID + 4);
                acc[0][0]=fmaf(a0,w0.x,acc[0][0]); acc[0][1]=fmaf(a0,w0.y,acc[0][1]);
                acc[0][2]=fmaf(a0,w0.z,acc[0][2]); acc[0][3]=fmaf(a0,w0.w,acc[0][3]);
                acc[0][4]=fmaf(a0,w1.x,acc[0][4]); acc[0][5]=fmaf(a0,w1.y,acc[0][5]);
                acc[0][6]=fmaf(a0,w1.z,acc[0][6]); acc[0][7]=fmaf(a0,w1.w,acc[0][7]);
                acc[1][0]=fmaf(a1,w0.x,acc[1][0]); acc[1][1]=fmaf(a1,w0.y,acc[1][1]);
                acc[1][2]=fmaf(a1,w0.z,acc[1][2]); acc[1][3]=fmaf(a1,w0.w,acc[1][3]);
                acc[1][4]=fmaf(a1,w1.x,acc[1][4]); acc[1][5]=fmaf(a1,w1.y,acc[1][5]);
                acc[1][6]=fmaf(a1,w1.z,acc[1][6]); acc[1][7]=fmaf(a1,w1.w,acc[1][7]);
            }
        }
    }
#pragma unroll
    for (int m = 0; m < 2; m++) {
        float4 o0, o1;
        o0.x=gelu_f(acc[m][0]); o0.y=gelu_f(acc[m][1]); o0.z=gelu_f(acc[m][2]); o0.w=gelu_f(acc[m][3]);
        o1.x=gelu_f(acc[m][4]); o1.y=gelu_f(acc[m][5]); o1.z=gelu_f(acc[m][6]); o1.w=gelu_f(acc[m][7]);
        float* dst = &g_g1[((n*H1v+oy)*W1v + x0 + xl + 16*m)*HID + co];
        *reinterpret_cast<float4*>(dst)     = o0;
        *reinterpret_cast<float4*>(dst + 4) = o1;
    }
}

// ================= convt2 + gelu + 1x1(128->3): g1 -> x_rec in d_out =================
// block = 256 threads, tile 32 out px x 128 co. grid (8,256,16).
#define CT2 132
__global__ void k_convt2(const float* __restrict__ w, const float* __restrict__ b,
                         const float* __restrict__ w3, const float* __restrict__ b3,
                         float* __restrict__ dout) {
    __shared__ float ins[2*18*CT2];   // 4752 floats
    __shared__ float gs[32*CT2];      // 4224 floats
    float* red = ins;                 // reused after main loop
    int tid = threadIdx.x;
    int bx = blockIdx.x, oy = blockIdx.y, n = blockIdx.z;
    int x0 = bx * 32;
    int kyA = (oy & 1);
    int iy0 = (oy + kyA - 2) >> 1;
    int c0 = (x0 >> 1) - 1;
    for (int i = tid; i < 2*18*32; i += 256) {
        int r = i / (18*32); int rem = i - r*(18*32); int c = rem >> 5; int d4 = rem & 31;
        int iy = iy0 + r; int ix = c0 + c;
        float4 v = make_float4(0,0,0,0);
        if (iy >= 0 && iy < H1v && ix >= 0 && ix < W1v)
            v = *reinterpret_cast<const float4*>(&g_g1[((n*H1v+iy)*W1v+ix)*HID + 4*d4]);
        *reinterpret_cast<float4*>(&ins[(r*18+c)*CT2 + 4*d4]) = v;
    }
    __syncthreads();
    int p = tid & 15;
    int par = p >> 3;
    int q = p & 7;
    int xl = 2*q + par;
    int co = (tid >> 4) * 8;
    float acc[2][8];
    {
        float4 b0 = *reinterpret_cast<const float4*>(&b[co]);
        float4 b1 = *reinterpret_cast<const float4*>(&b[co+4]);
#pragma unroll
        for (int m = 0; m < 2; m++) {
            acc[m][0]=b0.x; acc[m][1]=b0.y; acc[m][2]=b0.z; acc[m][3]=b0.w;
            acc[m][4]=b1.x; acc[m][5]=b1.y; acc[m][6]=b1.z; acc[m][7]=b1.w;
        }
    }
    int kxA = par;
#pragma unroll
    for (int kyi = 0; kyi < 2; kyi++) {
        int ky = kyA + 2*kyi;
#pragma unroll
        for (int kxi = 0; kxi < 2; kxi++) {
            int kx = kxA + 2*kxi;
            int c = (xl + kx) >> 1;
            const float* i0 = &ins[(kyi*18 + c)*CT2];
            const float* i1 = i0 + 8*CT2;
            const float* wr = &w[((ky*4+kx)*HID)*HID + co];
#pragma unroll 4
            for (int ci = 0; ci < 128; ci++) {
                float a0 = i0[ci], a1 = i1[ci];
                float4 w0 = *reinterpret_cast<const float4*>(wr + ci*HID);
                float4 w1 = *reinterpret_cast<const float4*>(wr + ci*HID + 4);
                acc[0][0]=fmaf(a0,w0.x,acc[0][0]); acc[0][1]=fmaf(a0,w0.y,acc[0][1]);
                acc[0][2]=fmaf(a0,w0.z,acc[0][2]); acc[0][3]=fmaf(a0,w0.w,acc[0][3]);
                acc[0][4]=fmaf(a0,w1.x,acc[0][4]); acc[0][5]=fmaf(a0,w1.y,acc[0][5]);
                acc[0][6]=fmaf(a0,w1.z,acc[0][6]); acc[0][7]=fmaf(a0,w1.w,acc[0][7]);
                acc[1][0]=fmaf(a1,w0.x,acc[1][0]); acc[1][1]=fmaf(a1,w0.y,acc[1][1]);
                acc[1][2]=fmaf(a1,w0.z,acc[1][2]); acc[1][3]=fmaf(a1,w0.w,acc[1][3]);
                acc[1][4]=fmaf(a1,w1.x,acc[1][4]); acc[1][5]=fmaf(a1,w1.y,acc[1][5]);
                acc[1][6]=fmaf(a1,w1.z,acc[1][6]); acc[1][7]=fmaf(a1,w1.w,acc[1][7]);
            }
        }
    }
    // gelu -> smem tile [32 px][128 co]
#pragma unroll
    for (int m = 0; m < 2; m++) {
        float4 o0, o1;
        o0.x=gelu_f(acc[m][0]); o0.y=gelu_f(acc[m][1]); o0.z=gelu_f(acc[m][2]); o0.w=gelu_f(acc[m][3]);
        o1.x=gelu_f(acc[m][4]); o1.y=gelu_f(acc[m][5]); o1.z=gelu_f(acc[m][6]); o1.w=gelu_f(acc[m][7]);
        *reinterpret_cast<float4*>(&gs[(xl + 16*m)*CT2 + co])     = o0;
        *reinterpret_cast<float4*>(&gs[(xl + 16*m)*CT2 + co + 4]) = o1;
    }
    __syncthreads();
    // fused 1x1: 128 -> 3 per pixel (partials over 16-co chunks, then reduce)
    {
        int px = tid & 31;
        int g8 = tid >> 5;   // 0..7
        float p0 = 0.0f, p1 = 0.0f, p2 = 0.0f;
        const float* gp = &gs[px*CT2 + g8*16];
        const float* wp = &w3[g8*16*3];
#pragma unroll
        for (int k = 0; k < 16; k++) {
            float gv = gp[k];
            p0 = fmaf(gv, wp[k*3+0], p0);
            p1 = fmaf(gv, wp[k*3+1], p1);
            p2 = fmaf(gv, wp[k*3+2], p2);
        }
        red[(px*8 + g8)*3 + 0] = p0;
        red[(px*8 + g8)*3 + 1] = p1;
        red[(px*8 + g8)*3 + 2] = p2;
    }
    __syncthreads();
    if (tid < 96) {
        int px = tid / 3; int c = tid - px*3;
        float s = b3[c];
#pragma unroll
        for (int k = 0; k < 8; k++) s += red[(px*8 + k)*3 + c];
        dout[((n*H0+oy)*W0 + x0 + px)*3 + c] = s;
    }
}

// ================= finalize losses =================
__global__ void k_final(float* __restrict__ dout) {
    float l = g_loss / (float)(TOK_ELEMS * EMB);
    dout[LOSS_OFF]     = l;
    dout[LOSS_OFF + 1] = l;
}

// ================= launch =================
extern "C" void kernel_launch(void* const* d_in, const int* in_sizes, int n_in,
                              void* d_out, int out_size) {
    const float* x      = (const float*)d_in[0];
    const float* enc_w1 = (const float*)d_in[1];
    const float* enc_b1 = (const float*)d_in[2];
    const float* enc_w2 = (const float*)d_in[3];
    const float* enc_b2 = (const float*)d_in[4];
    const float* enc_w3 = (const float*)d_in[5];
    const float* enc_b3 = (const float*)d_in[6];
    const float* cb     = (const float*)d_in[7];
    const float* dec_w1 = (const float*)d_in[8];
    const float* dec_b1 = (const float*)d_in[9];
    const float* dec_w2 = (const float*)d_in[10];
    const float* dec_b2 = (const float*)d_in[11];
    const float* dec_w3 = (const float*)d_in[12];
    const float* dec_b3 = (const float*)d_in[13];
    float* out = (float*)d_out;

    static int smem_set = 0;
    const int smem2 = (INS2 + 16*132) * 4;   // 79168 B
    if (!smem_set) {
        cudaFuncSetAttribute(k_conv2, cudaFuncAttributeMaxDynamicSharedMemorySize, smem2);
        smem_set = 1;
    }

    k_conv1<<<dim3(8, 128, 16), 128>>>(x, enc_w1, enc_b1);
    k_conv2<<<dim3(4, 64, 16), 256, smem2>>>(enc_w2, enc_b2, enc_w3, enc_b3);
    k_vq<<<4096, 128>>>(cb, out);
    k_convt1<<<dim3(4, 128, 16), 256>>>(dec_w1, dec_b1);
    k_convt2<<<dim3(8, 256, 16), 256>>>(dec_w2, dec_b2, dec_w3, dec_b3, out);
    k_final<<<1, 1>>>(out);
}

// round 3
// speedup vs baseline: 2.0315x; 2.0315x over previous
#include <cuda_runtime.h>
#include <math.h>

// ---------------- sizes ----------------
#define BATCH 16
#define H0 256
#define W0 256
#define CIN 3
#define HID 128
#define EMB 64
#define KCODES 1024
#define H1v 128
#define W1v 128
#define H2v 64
#define W2v 64

#define XREC_ELEMS (BATCH*H0*W0*3)      // 3145728
#define TOK_OFF    XREC_ELEMS
#define TOK_ELEMS  (BATCH*H2v*W2v)      // 65536
#define LOSS_OFF   (TOK_OFF + TOK_ELEMS)

// ---------------- scratch ----------------
__device__ float g_h1[BATCH*H1v*W1v*HID];   // encoder conv1 out (gelu'd)
__device__ float g_ze[BATCH*H2v*W2v*EMB];   // z_e
__device__ float g_zst[BATCH*H2v*W2v*EMB];  // z_st
__device__ float g_g1[BATCH*H1v*W1v*HID];   // decoder convt1 out (gelu'd)
__device__ float g_loss;

__device__ __forceinline__ float gelu_f(float x) {
    float t = 0.7978845608028654f * (x + 0.044715f * x * x * x);
    return 0.5f * x * (1.0f + tanhf(t));
}

#define FMA8(J, AJ) \
    acc[J][0]=fmaf(AJ,w0.x,acc[J][0]); acc[J][1]=fmaf(AJ,w0.y,acc[J][1]); \
    acc[J][2]=fmaf(AJ,w0.z,acc[J][2]); acc[J][3]=fmaf(AJ,w0.w,acc[J][3]); \
    acc[J][4]=fmaf(AJ,w1.x,acc[J][4]); acc[J][5]=fmaf(AJ,w1.y,acc[J][5]); \
    acc[J][6]=fmaf(AJ,w1.z,acc[J][6]); acc[J][7]=fmaf(AJ,w1.w,acc[J][7]);

// ================= conv1: x[16,256,256,3] -> h1[16,128,128,128], 4x4 s2 SAME, gelu =================
__global__ void k_conv1(const float* __restrict__ x, const float* __restrict__ w,
                        const float* __restrict__ b) {
    __shared__ float ws[4*4*3*128];   // 24 KB
    __shared__ float ins[4*34*3];     // input tile
    int tid = threadIdx.x;
    int bx = blockIdx.x, oy = blockIdx.y, n = blockIdx.z;
    if (bx == 0 && oy == 0 && n == 0 && tid == 0) g_loss = 0.0f;
    for (int i = tid; i < 6144; i += 128) ws[i] = w[i];
    int x0 = bx * 16;
    for (int i = tid; i < 4*34*3; i += 128) {
        int r = i / (34*3); int rem = i - r*(34*3); int c = rem / 3; int ch = rem % 3;
        int gy = 2*oy - 1 + r;
        int gx = 2*x0 - 1 + c;
        float v = 0.0f;
        if (gy >= 0 && gy < H0 && gx >= 0 && gx < W0) v = x[((n*H0+gy)*W0+gx)*CIN + ch];
        ins[i] = v;
    }
    __syncthreads();
    int co = tid;
    float bias = b[co];
    float acc[16];
#pragma unroll
    for (int p = 0; p < 16; p++) acc[p] = bias;
    for (int ky = 0; ky < 4; ky++) {
        for (int kx = 0; kx < 4; kx++) {
#pragma unroll
            for (int ci = 0; ci < 3; ci++) {
                float wv = ws[((ky*4+kx)*3+ci)*128 + co];
#pragma unroll
                for (int p = 0; p < 16; p++) {
                    acc[p] = fmaf(ins[(ky*34 + 2*p + kx)*3 + ci], wv, acc[p]);
                }
            }
        }
    }
#pragma unroll
    for (int p = 0; p < 16; p++) {
        g_h1[((n*H1v+oy)*W1v + x0 + p)*HID + co] = gelu_f(acc[p]);
    }
}

// ================= conv2 (GEMM-tiled) + gelu + 1x1(128->64): h1 -> z_e =================
// block = 128 threads. tile: 64 ox (one row) x 128 co. grid (64 oy, 16 n).
// K = 16 taps x 128 ci, chunked by 4 ci.
__global__ void __launch_bounds__(128) k_conv2(const float* __restrict__ w2, const float* __restrict__ b2,
                                               const float* __restrict__ w3, const float* __restrict__ b3) {
    __shared__ float sm[2112 + 8192];       // ins [4r][4cik][132] | Bs [16tap][4cik][128]
    float* ins = sm;
    float* Bs  = sm + 2112;
    float* h2s = sm;                        // reused after main loop: [64 px][132]
    int tid = threadIdx.x;
    int oy = blockIdx.x, n = blockIdx.y;
    int pa = tid & 7, cg = tid >> 3;        // pa: px group, cg: co group (0..15)
    int co0 = cg * 8;
    float acc[8][8];
    {
        float4 b0 = *reinterpret_cast<const float4*>(&b2[co0]);
        float4 b1 = *reinterpret_cast<const float4*>(&b2[co0+4]);
#pragma unroll
        for (int j = 0; j < 8; j++) {
            acc[j][0]=b0.x; acc[j][1]=b0.y; acc[j][2]=b0.z; acc[j][3]=b0.w;
            acc[j][4]=b1.x; acc[j][5]=b1.y; acc[j][6]=b1.z; acc[j][7]=b1.w;
        }
    }
    int axbase = 2 * pa;
#pragma unroll 1
    for (int ch = 0; ch < 32; ch++) {
        int ci0 = ch * 4;
        // stage inputs: 4 rows x 130 ixl x (4 ci, transposed to planes)
        for (int i = tid; i < 520; i += 128) {
            int r = i / 130; int ixl = i - r*130;
            int iy = 2*oy - 1 + r;
            int ix = ixl - 1;
            float4 v = make_float4(0,0,0,0);
            if (iy >= 0 && iy < H1v && ix >= 0 && ix < W1v)
                v = *reinterpret_cast<const float4*>(&g_h1[((n*H1v+iy)*W1v+ix)*HID + ci0]);
            float* dst = &ins[(r*4)*132 + ixl];
            dst[0] = v.x; dst[132] = v.y; dst[264] = v.z; dst[396] = v.w;
        }
        // stage weights: 16 taps x 4 cik x 128 co
        for (int i = tid; i < 2048; i += 128) {
            int co4 = i & 31; int cik = (i >> 5) & 3; int tap = i >> 7;
            float4 wv = *reinterpret_cast<const float4*>(&w2[((tap*HID) + ci0 + cik)*HID + co4*4]);
            *reinterpret_cast<float4*>(&Bs[(tap*4+cik)*128 + co4*4]) = wv;
        }
        __syncthreads();
        for (int tap = 0; tap < 16; tap++) {
            int kx = tap & 3; int row = tap >> 2;
#pragma unroll
            for (int cik = 0; cik < 4; cik++) {
                const float* bp = &Bs[(tap*4+cik)*128 + co0];
                float4 w0 = *reinterpret_cast<const float4*>(bp);
                float4 w1 = *reinterpret_cast<const float4*>(bp + 4);
                const float* ap = &ins[(row*4+cik)*132 + axbase + kx];
                float a0 = ap[0],  a1 = ap[16], a2 = ap[32], a3 = ap[48];
                float a4 = ap[64], a5 = ap[80], a6 = ap[96], a7 = ap[112];
                FMA8(0,a0) FMA8(1,a1) FMA8(2,a2) FMA8(3,a3)
                FMA8(4,a4) FMA8(5,a5) FMA8(6,a6) FMA8(7,a7)
            }
        }
        __syncthreads();
    }
    // gelu -> h2s [64 px][132]
#pragma unroll
    for (int j = 0; j < 8; j++) {
        int ox = pa + 8*j;
        float4 o0, o1;
        o0.x=gelu_f(acc[j][0]); o0.y=gelu_f(acc[j][1]); o0.z=gelu_f(acc[j][2]); o0.w=gelu_f(acc[j][3]);
        o1.x=gelu_f(acc[j][4]); o1.y=gelu_f(acc[j][5]); o1.z=gelu_f(acc[j][6]); o1.w=gelu_f(acc[j][7]);
        *reinterpret_cast<float4*>(&h2s[ox*132 + co0])     = o0;
        *reinterpret_cast<float4*>(&h2s[ox*132 + co0 + 4]) = o1;
    }
    __syncthreads();
    // fused 1x1: 128 -> 64, each thread: one px-half, 32 embeds
    {
        int px = tid >> 1;
        int e0 = (tid & 1) * 32;
        float z[32];
#pragma unroll
        for (int u = 0; u < 8; u++) {
            float4 bb = *reinterpret_cast<const float4*>(&b3[e0 + 4*u]);
            z[4*u]=bb.x; z[4*u+1]=bb.y; z[4*u+2]=bb.z; z[4*u+3]=bb.w;
        }
#pragma unroll 4
        for (int ci = 0; ci < 128; ci++) {
            float hv = h2s[px*132 + ci];
#pragma unroll
            for (int u = 0; u < 8; u++) {
                float4 wv = *reinterpret_cast<const float4*>(&w3[ci*EMB + e0 + 4*u]);
                z[4*u]  = fmaf(hv, wv.x, z[4*u]);   z[4*u+1] = fmaf(hv, wv.y, z[4*u+1]);
                z[4*u+2]= fmaf(hv, wv.z, z[4*u+2]); z[4*u+3] = fmaf(hv, wv.w, z[4*u+3]);
            }
        }
        float* dst = &g_ze[((n*H2v+oy)*W2v + px)*EMB + e0];
#pragma unroll
        for (int u = 0; u < 8; u++)
            *reinterpret_cast<float4*>(dst + 4*u) = make_float4(z[4*u], z[4*u+1], z[4*u+2], z[4*u+3]);
    }
}

// ================= VQ: argmin over 1024 codes, tok + z_st + loss =================
#define CSTR 68
__global__ void k_vq(const float* __restrict__ cb, float* __restrict__ dout) {
    __shared__ float cs[64*CSTR];
    __shared__ float e2s[64];
    __shared__ float bval[128];
    __shared__ int   bidx[128];
    __shared__ int   widx[16];
    __shared__ float lred[128];
    int tid = threadIdx.x;
    int pb = blockIdx.x * 16;
    int p = tid & 15;
    int g = tid >> 4;   // 0..7
    float4 z4[16];
    const float* zp = &g_ze[(pb + p)*EMB];
#pragma unroll
    for (int i = 0; i < 16; i++) z4[i] = *reinterpret_cast<const float4*>(&zp[4*i]);
    float best = 3.4e38f; int bi = 0;
    for (int ch = 0; ch < 16; ch++) {
        for (int i = tid; i < 64*16; i += 128) {
            int cj = i >> 4; int d4 = i & 15;
            float4 v = *reinterpret_cast<const float4*>(&cb[(ch*64+cj)*EMB + 4*d4]);
            *reinterpret_cast<float4*>(&cs[cj*CSTR + 4*d4]) = v;
        }
        __syncthreads();
        if (tid < 64) {
            float s = 0.0f;
#pragma unroll 8
            for (int d = 0; d < 64; d++) { float c = cs[tid*CSTR + d]; s = fmaf(c, c, s); }
            e2s[tid] = s;
        }
        __syncthreads();
#pragma unroll
        for (int j = 0; j < 8; j++) {
            int cj = g*8 + j;
            const float* cp = &cs[cj*CSTR];
            float dot = 0.0f;
#pragma unroll
            for (int i = 0; i < 16; i++) {
                float4 c = *reinterpret_cast<const float4*>(&cp[4*i]);
                dot = fmaf(z4[i].x, c.x, dot); dot = fmaf(z4[i].y, c.y, dot);
                dot = fmaf(z4[i].z, c.z, dot); dot = fmaf(z4[i].w, c.w, dot);
            }
            float dist = e2s[cj] - 2.0f*dot;
            int gidx = ch*64 + cj;
            if (dist < best || (dist == best && gidx < bi)) { best = dist; bi = gidx; }
        }
        __syncthreads();
    }
    bval[tid] = best; bidx[tid] = bi;
    __syncthreads();
    if (tid < 16) {
        float bb = bval[tid]; int bbi = bidx[tid];
        for (int k = 1; k < 8; k++) {
            float v = bval[tid + 16*k]; int vi = bidx[tid + 16*k];
            if (v < bb || (v == bb && vi < bbi)) { bb = v; bbi = vi; }
        }
        widx[tid] = bbi;
        dout[TOK_OFF + pb + tid] = (float)bbi;
    }
    __syncthreads();
    int idx = widx[p];
    float lsum = 0.0f;
    const float* cq = &cb[idx*EMB + g*8];
    const float* ze = &g_ze[(pb + p)*EMB + g*8];
    float*       zs = &g_zst[(pb + p)*EMB + g*8];
#pragma unroll
    for (int d = 0; d < 8; d++) {
        float zq = cq[d]; float z = ze[d];
        float diff = zq - z;
        zs[d] = z + diff;
        lsum = fmaf(diff, diff, lsum);
    }
    lred[tid] = lsum;
    __syncthreads();
    for (int s = 64; s > 0; s >>= 1) {
        if (tid < s) lred[tid] += lred[tid + s];
        __syncthreads();
    }
    if (tid == 0) atomicAdd(&g_loss, lred[0]);
}

// ================= convt1 (GEMM-tiled): z_st -> g1 (gelu) =================
// block = 256 threads. tile: 128 ox (one row) x 128 co. grid (128 oy, 16 n).
// K = 2 kyi x 2 kxi x 64 ci, chunked by 8 ci.
__global__ void __launch_bounds__(256) k_convt1(const float* __restrict__ w, const float* __restrict__ b) {
    __shared__ float ins[1072];   // [kyi][cik][67] (66 used)
    __shared__ float Bs[8192];    // [(kyi*4+kx)*8+cik][128]
    int tid = threadIdx.x;
    int oy = blockIdx.x, n = blockIdx.y;
    int pgx = tid & 15, cg = tid >> 4;
    int par = pgx >> 3, pa = pgx & 7;
    int co0 = cg * 8;
    int kyA = oy & 1;
    int iy0 = (oy + kyA - 2) >> 1;
    float acc[8][8];
    {
        float4 b0 = *reinterpret_cast<const float4*>(&b[co0]);
        float4 b1 = *reinterpret_cast<const float4*>(&b[co0+4]);
#pragma unroll
        for (int j = 0; j < 8; j++) {
            acc[j][0]=b0.x; acc[j][1]=b0.y; acc[j][2]=b0.z; acc[j][3]=b0.w;
            acc[j][4]=b1.x; acc[j][5]=b1.y; acc[j][6]=b1.z; acc[j][7]=b1.w;
        }
    }
    int abase = 4*pa + par;
#pragma unroll 1
    for (int ch = 0; ch < 8; ch++) {
        int ci0 = ch * 8;
        for (int i = tid; i < 264; i += 256) {
            int kyi = i / 132; int r = i - kyi*132; int ixl = r >> 1; int f4 = r & 1;
            int iy = iy0 + kyi; int ix = ixl - 1;
            float4 v = make_float4(0,0,0,0);
            if (iy >= 0 && iy < H2v && ix >= 0 && ix < W2v)
                v = *reinterpret_cast<const float4*>(&g_zst[((n*H2v+iy)*W2v+ix)*EMB + ci0 + 4*f4]);
            float* dst = &ins[(kyi*8 + 4*f4)*67 + ixl];
            dst[0] = v.x; dst[67] = v.y; dst[134] = v.z; dst[201] = v.w;
        }
        for (int i = tid; i < 2048; i += 256) {
            int co4 = i & 31; int cik = (i >> 5) & 7; int kx = (i >> 8) & 3; int kyi = i >> 10;
            int ky = kyA + 2*kyi;
            float4 wv = *reinterpret_cast<const float4*>(&w[(((ky*4+kx)*EMB) + ci0 + cik)*HID + co4*4]);
            *reinterpret_cast<float4*>(&Bs[((kyi*4+kx)*8+cik)*128 + co4*4]) = wv;
        }
        __syncthreads();
#pragma unroll
        for (int cik = 0; cik < 8; cik++) {
#pragma unroll
            for (int kyi = 0; kyi < 2; kyi++) {
#pragma unroll
                for (int kxi = 0; kxi < 2; kxi++) {
                    int kx = par + 2*kxi;
                    const float* bp = &Bs[((kyi*4+kx)*8+cik)*128 + co0];
                    float4 w0 = *reinterpret_cast<const float4*>(bp);
                    float4 w1 = *reinterpret_cast<const float4*>(bp + 4);
                    const float* ap = &ins[(kyi*8+cik)*67 + abase + kxi];
                    float a0 = ap[0],  a1 = ap[1],  a2 = ap[2],  a3 = ap[3];
                    float a4 = ap[32], a5 = ap[33], a6 = ap[34], a7 = ap[35];
                    FMA8(0,a0) FMA8(1,a1) FMA8(2,a2) FMA8(3,a3)
                    FMA8(4,a4) FMA8(5,a5) FMA8(6,a6) FMA8(7,a7)
                }
            }
        }
        __syncthreads();
    }
#pragma unroll
    for (int j = 0; j < 8; j++) {
        int mxl = (j < 4) ? (4*pa + j) : (32 + 4*pa + j - 4);
        int ox = 2*mxl + par;
        float4 o0, o1;
        o0.x=gelu_f(acc[j][0]); o0.y=gelu_f(acc[j][1]); o0.z=gelu_f(acc[j][2]); o0.w=gelu_f(acc[j][3]);
        o1.x=gelu_f(acc[j][4]); o1.y=gelu_f(acc[j][5]); o1.z=gelu_f(acc[j][6]); o1.w=gelu_f(acc[j][7]);
        float* dst = &g_g1[((n*H1v+oy)*W1v + ox)*HID + co0];
        *reinterpret_cast<float4*>(dst)     = o0;
        *reinterpret_cast<float4*>(dst + 4) = o1;
    }
}

// ================= convt2 (GEMM-tiled) + gelu + 1x1(128->3): g1 -> x_rec =================
// block = 256 threads. tile: 128 ox x 128 co. grid (2 bx, 256 oy, 16 n). dyn smem.
__global__ void __launch_bounds__(256) k_convt2(const float* __restrict__ w, const float* __restrict__ b,
                                                const float* __restrict__ w3, const float* __restrict__ b3,
                                                float* __restrict__ dout) {
    extern __shared__ float sm[];
    float* ins = sm;            // 1072: [kyi][cik][67]
    float* Bs  = sm + 1072;     // 8192
    float* gs  = sm;            // reused: [128 px][132]
    int tid = threadIdx.x;
    int bx = blockIdx.x, oy = blockIdx.y, n = blockIdx.z;
    int x0 = bx * 128, xb = bx * 64;
    int pgx = tid & 15, cg = tid >> 4;
    int par = pgx >> 3, pa = pgx & 7;
    int co0 = cg * 8;
    int kyA = oy & 1;
    int iy0 = (oy + kyA - 2) >> 1;
    float acc[8][8];
    {
        float4 b0 = *reinterpret_cast<const float4*>(&b[co0]);
        float4 b1 = *reinterpret_cast<const float4*>(&b[co0+4]);
#pragma unroll
        for (int j = 0; j < 8; j++) {
            acc[j][0]=b0.x; acc[j][1]=b0.y; acc[j][2]=b0.z; acc[j][3]=b0.w;
            acc[j][4]=b1.x; acc[j][5]=b1.y; acc[j][6]=b1.z; acc[j][7]=b1.w;
        }
    }
    int abase = 4*pa + par;
#pragma unroll 1
    for (int ch = 0; ch < 16; ch++) {
        int ci0 = ch * 8;
        for (int i = tid; i < 264; i += 256) {
            int kyi = i / 132; int r = i - kyi*132; int ixl = r >> 1; int f4 = r & 1;
            int iy = iy0 + kyi; int ix = xb + ixl - 1;
            float4 v = make_float4(0,0,0,0);
            if (iy >= 0 && iy < H1v && ix >= 0 && ix < W1v)
                v = *reinterpret_cast<const float4*>(&g_g1[((n*H1v+iy)*W1v+ix)*HID + ci0 + 4*f4]);
            float* dst = &ins[(kyi*8 + 4*f4)*67 + ixl];
            dst[0] = v.x; dst[67] = v.y; dst[134] = v.z; dst[201] = v.w;
        }
        for (int i = tid; i < 2048; i += 256) {
            int co4 = i & 31; int cik = (i >> 5) & 7; int kx = (i >> 8) & 3; int kyi = i >> 10;
            int ky = kyA + 2*kyi;
            float4 wv = *reinterpret_cast<const float4*>(&w[(((ky*4+kx)*HID) + ci0 + cik)*HID + co4*4]);
            *reinterpret_cast<float4*>(&Bs[((kyi*4+kx)*8+cik)*128 + co4*4]) = wv;
        }
        __syncthreads();
#pragma unroll
        for (int cik = 0; cik < 8; cik++) {
#pragma unroll
            for (int kyi = 0; kyi < 2; kyi++) {
#pragma unroll
                for (int kxi = 0; kxi < 2; kxi++) {
                    int kx = par + 2*kxi;
                    const float* bp = &Bs[((kyi*4+kx)*8+cik)*128 + co0];
                    float4 w0 = *reinterpret_cast<const float4*>(bp);
                    float4 w1 = *reinterpret_cast<const float4*>(bp + 4);
                    const float* ap = &ins[(kyi*8+cik)*67 + abase + kxi];
                    float a0 = ap[0],  a1 = ap[1],  a2 = ap[2],  a3 = ap[3];
                    float a4 = ap[32], a5 = ap[33], a6 = ap[34], a7 = ap[35];
                    FMA8(0,a0) FMA8(1,a1) FMA8(2,a2) FMA8(3,a3)
                    FMA8(4,a4) FMA8(5,a5) FMA8(6,a6) FMA8(7,a7)
                }
            }
        }
        __syncthreads();
    }
    // gelu -> gs [128 px][132]
#pragma unroll
    for (int j = 0; j < 8; j++) {
        int mxl = (j < 4) ? (4*pa + j) : (32 + 4*pa + j - 4);
        int ox = 2*mxl + par;
        float4 o0, o1;
        o0.x=gelu_f(acc[j][0]); o0.y=gelu_f(acc[j][1]); o0.z=gelu_f(acc[j][2]); o0.w=gelu_f(acc[j][3]);
        o1.x=gelu_f(acc[j][4]); o1.y=gelu_f(acc[j][5]); o1.z=gelu_f(acc[j][6]); o1.w=gelu_f(acc[j][7]);
        *reinterpret_cast<float4*>(&gs[ox*132 + co0])     = o0;
        *reinterpret_cast<float4*>(&gs[ox*132 + co0 + 4]) = o1;
    }
    __syncthreads();
    // fused 1x1: 128 -> 3. 2 threads per px, shfl combine.
    {
        int px = tid >> 1;
        int half = tid & 1;
        float p0 = 0.0f, p1 = 0.0f, p2 = 0.0f;
        const float* gp = &gs[px*132 + half*64];
        const float* wp = &w3[half*64*3];
#pragma unroll 8
        for (int k = 0; k < 64; k++) {
            float gv = gp[k];
            p0 = fmaf(gv, wp[3*k+0], p0);
            p1 = fmaf(gv, wp[3*k+1], p1);
            p2 = fmaf(gv, wp[3*k+2], p2);
        }
        p0 += __shfl_xor_sync(0xffffffffu, p0, 1);
        p1 += __shfl_xor_sync(0xffffffffu, p1, 1);
        p2 += __shfl_xor_sync(0xffffffffu, p2, 1);
        if (half == 0) {
            float* dst = &dout[((n*H0+oy)*W0 + x0 + px)*3];
            dst[0] = p0 + b3[0];
            dst[1] = p1 + b3[1];
            dst[2] = p2 + b3[2];
        }
    }
}

// ================= finalize losses =================
__global__ void k_final(float* __restrict__ dout) {
    float l = g_loss / (float)(TOK_ELEMS * EMB);
    dout[LOSS_OFF]     = l;
    dout[LOSS_OFF + 1] = l;
}

// ================= launch =================
extern "C" void kernel_launch(void* const* d_in, const int* in_sizes, int n_in,
                              void* d_out, int out_size) {
    const float* x      = (const float*)d_in[0];
    const float* enc_w1 = (const float*)d_in[1];
    const float* enc_b1 = (const float*)d_in[2];
    const float* enc_w2 = (const float*)d_in[3];
    const float* enc_b2 = (const float*)d_in[4];
    const float* enc_w3 = (const float*)d_in[5];
    const float* enc_b3 = (const float*)d_in[6];
    const float* cb     = (const float*)d_in[7];
    const float* dec_w1 = (const float*)d_in[8];
    const float* dec_b1 = (const float*)d_in[9];
    const float* dec_w2 = (const float*)d_in[10];
    const float* dec_b2 = (const float*)d_in[11];
    const float* dec_w3 = (const float*)d_in[12];
    const float* dec_b3 = (const float*)d_in[13];
    float* out = (float*)d_out;

    static int smem_set = 0;
    const int smem_t2 = 128*132*4;   // gs [128][132] = 67584 B
    if (!smem_set) {
        cudaFuncSetAttribute(k_convt2, cudaFuncAttributeMaxDynamicSharedMemorySize, smem_t2);
        smem_set = 1;
    }

    k_conv1<<<dim3(8, 128, 16), 128>>>(x, enc_w1, enc_b1);
    k_conv2<<<dim3(64, 16), 128>>>(enc_w2, enc_b2, enc_w3, enc_b3);
    k_vq<<<4096, 128>>>(cb, out);
    k_convt1<<<dim3(128, 16), 256>>>(dec_w1, dec_b1);
    k_convt2<<<dim3(2, 256, 16), 256, smem_t2>>>(dec_w2, dec_b2, dec_w3, dec_b3, out);
    k_final<<<1, 1>>>(out);
}

// round 4
// speedup vs baseline: 2.2078x; 1.0868x over previous
#include <cuda_runtime.h>
#include <math.h>

// ---------------- sizes ----------------
#define BATCH 16
#define H0 256
#define W0 256
#define CIN 3
#define HID 128
#define EMB 64
#define KCODES 1024
#define H1v 128
#define W1v 128
#define H2v 64
#define W2v 64

#define XREC_ELEMS (BATCH*H0*W0*3)      // 3145728
#define TOK_OFF    XREC_ELEMS
#define TOK_ELEMS  (BATCH*H2v*W2v)      // 65536
#define LOSS_OFF   (TOK_OFF + TOK_ELEMS)

typedef unsigned long long u64;

// ---------------- scratch ----------------
__device__ float g_h1[BATCH*H1v*W1v*HID];   // encoder conv1 out (gelu'd)
__device__ float g_ze[BATCH*H2v*W2v*EMB];   // z_e
__device__ float g_zst[BATCH*H2v*W2v*EMB];  // z_st
__device__ float g_g1[BATCH*H1v*W1v*HID];   // decoder convt1 out (gelu'd)
__device__ float g_loss;

__device__ __forceinline__ float gelu_f(float x) {
    float t = 0.7978845608028654f * (x + 0.044715f * x * x * x);
    return 0.5f * x * (1.0f + tanhf(t));
}

// ---------------- packed f32x2 helpers ----------------
__device__ __forceinline__ u64 splat2(float a) {
    u64 r; asm("mov.b64 %0, {%1, %1};" : "=l"(r) : "f"(a)); return r;
}
__device__ __forceinline__ u64 pack2(float lo, float hi) {
    u64 r; asm("mov.b64 %0, {%1, %2};" : "=l"(r) : "f"(lo), "f"(hi)); return r;
}
__device__ __forceinline__ void unpack2(u64 v, float& lo, float& hi) {
    asm("mov.b64 {%0, %1}, %2;" : "=f"(lo), "=f"(hi) : "l"(v));
}
__device__ __forceinline__ void ffma2(u64& d, u64 a, u64 b) {
    asm("fma.rn.f32x2 %0, %1, %2, %0;" : "+l"(d) : "l"(a), "l"(b));
}

// FFMA2 over 8 co (4 packed pairs) for one a-scalar
#define FFMA2_8(J, AJ) { u64 s_ = splat2(AJ); \
    ffma2(acc2[J][0], s_, w01); ffma2(acc2[J][1], s_, w23); \
    ffma2(acc2[J][2], s_, w45); ffma2(acc2[J][3], s_, w67); }

// ================= conv1: x[16,256,256,3] -> h1[16,128,128,128], 4x4 s2 SAME, gelu =================
__global__ void k_conv1(const float* __restrict__ x, const float* __restrict__ w,
                        const float* __restrict__ b) {
    __shared__ float ws[4*4*3*128];   // 24 KB
    __shared__ float ins[4*34*3];     // input tile
    int tid = threadIdx.x;
    int bx = blockIdx.x, oy = blockIdx.y, n = blockIdx.z;
    if (bx == 0 && oy == 0 && n == 0 && tid == 0) g_loss = 0.0f;
    for (int i = tid; i < 6144; i += 128) ws[i] = w[i];
    int x0 = bx * 16;
    for (int i = tid; i < 4*34*3; i += 128) {
        int r = i / (34*3); int rem = i - r*(34*3); int c = rem / 3; int ch = rem % 3;
        int gy = 2*oy - 1 + r;
        int gx = 2*x0 - 1 + c;
        float v = 0.0f;
        if (gy >= 0 && gy < H0 && gx >= 0 && gx < W0) v = x[((n*H0+gy)*W0+gx)*CIN + ch];
        ins[i] = v;
    }
    __syncthreads();
    int co = tid;
    float bias = b[co];
    u64 acc2[8];
#pragma unroll
    for (int pp = 0; pp < 8; pp++) acc2[pp] = pack2(bias, bias);
    for (int ky = 0; ky < 4; ky++) {
        for (int kx = 0; kx < 4; kx++) {
#pragma unroll
            for (int ci = 0; ci < 3; ci++) {
                float wv = ws[((ky*4+kx)*3+ci)*128 + co];
                u64 wvv = splat2(wv);
#pragma unroll
                for (int pp = 0; pp < 8; pp++) {
                    u64 av = pack2(ins[(ky*34 + 4*pp + kx)*3 + ci],
                                   ins[(ky*34 + 4*pp + 2 + kx)*3 + ci]);
                    ffma2(acc2[pp], av, wvv);
                }
            }
        }
    }
#pragma unroll
    for (int pp = 0; pp < 8; pp++) {
        float v0, v1; unpack2(acc2[pp], v0, v1);
        g_h1[((n*H1v+oy)*W1v + x0 + 2*pp)*HID + co]     = gelu_f(v0);
        g_h1[((n*H1v+oy)*W1v + x0 + 2*pp + 1)*HID + co] = gelu_f(v1);
    }
}

// ================= conv2 (GEMM-tiled, f32x2) + gelu + 1x1(128->64): h1 -> z_e =================
// block = 128 threads. tile: 64 ox (one row) x 128 co. grid (64 oy, 16 n).
__global__ void __launch_bounds__(128) k_conv2(const float* __restrict__ w2, const float* __restrict__ b2,
                                               const float* __restrict__ w3, const float* __restrict__ b3) {
    __shared__ float sm[2112 + 8192];       // ins [4r][4cik][132] | Bs [16tap][4cik][128]
    float* ins = sm;
    float* Bs  = sm + 2112;
    float* h2s = sm;                        // reused after main loop: [64 px][132]
    int tid = threadIdx.x;
    int oy = blockIdx.x, n = blockIdx.y;
    int pa = tid & 7, cg = tid >> 3;        // pa: px group, cg: co group (0..15)
    int co0 = cg * 8;
    u64 acc2[8][4];
    {
        float4 b0 = *reinterpret_cast<const float4*>(&b2[co0]);
        float4 b1 = *reinterpret_cast<const float4*>(&b2[co0+4]);
        u64 p0 = pack2(b0.x,b0.y), p1 = pack2(b0.z,b0.w);
        u64 p2 = pack2(b1.x,b1.y), p3 = pack2(b1.z,b1.w);
#pragma unroll
        for (int j = 0; j < 8; j++) { acc2[j][0]=p0; acc2[j][1]=p1; acc2[j][2]=p2; acc2[j][3]=p3; }
    }
    int axbase = 2 * pa;
#pragma unroll 1
    for (int ch = 0; ch < 32; ch++) {
        int ci0 = ch * 4;
        for (int i = tid; i < 520; i += 128) {
            int r = i / 130; int ixl = i - r*130;
            int iy = 2*oy - 1 + r;
            int ix = ixl - 1;
            float4 v = make_float4(0,0,0,0);
            if (iy >= 0 && iy < H1v && ix >= 0 && ix < W1v)
                v = *reinterpret_cast<const float4*>(&g_h1[((n*H1v+iy)*W1v+ix)*HID + ci0]);
            float* dst = &ins[(r*4)*132 + ixl];
            dst[0] = v.x; dst[132] = v.y; dst[264] = v.z; dst[396] = v.w;
        }
        for (int i = tid; i < 2048; i += 128) {
            int co4 = i & 31; int cik = (i >> 5) & 3; int tap = i >> 7;
            float4 wv = *reinterpret_cast<const float4*>(&w2[((tap*HID) + ci0 + cik)*HID + co4*4]);
            *reinterpret_cast<float4*>(&Bs[(tap*4+cik)*128 + co4*4]) = wv;
        }
        __syncthreads();
        for (int tap = 0; tap < 16; tap++) {
            int kx = tap & 3; int row = tap >> 2;
#pragma unroll
            for (int cik = 0; cik < 4; cik++) {
                const u64* bp = reinterpret_cast<const u64*>(&Bs[(tap*4+cik)*128 + co0]);
                u64 w01 = bp[0], w23 = bp[1], w45 = bp[2], w67 = bp[3];
                const float* ap = &ins[(row*4+cik)*132 + axbase + kx];
                float a0 = ap[0],  a1 = ap[16], a2 = ap[32], a3 = ap[48];
                float a4 = ap[64], a5 = ap[80], a6 = ap[96], a7 = ap[112];
                FFMA2_8(0,a0) FFMA2_8(1,a1) FFMA2_8(2,a2) FFMA2_8(3,a3)
                FFMA2_8(4,a4) FFMA2_8(5,a5) FFMA2_8(6,a6) FFMA2_8(7,a7)
            }
        }
        __syncthreads();
    }
    // gelu -> h2s [64 px][132]
#pragma unroll
    for (int j = 0; j < 8; j++) {
        int ox = pa + 8*j;
        float f0,f1,f2,f3,f4,f5,f6,f7;
        unpack2(acc2[j][0], f0, f1); unpack2(acc2[j][1], f2, f3);
        unpack2(acc2[j][2], f4, f5); unpack2(acc2[j][3], f6, f7);
        float4 o0 = make_float4(gelu_f(f0), gelu_f(f1), gelu_f(f2), gelu_f(f3));
        float4 o1 = make_float4(gelu_f(f4), gelu_f(f5), gelu_f(f6), gelu_f(f7));
        *reinterpret_cast<float4*>(&h2s[ox*132 + co0])     = o0;
        *reinterpret_cast<float4*>(&h2s[ox*132 + co0 + 4]) = o1;
    }
    __syncthreads();
    // fused 1x1: 128 -> 64, each thread: one px-half, 32 embeds (f32x2)
    {
        int px = tid >> 1;
        int e0 = (tid & 1) * 32;
        u64 z2[16];
#pragma unroll
        for (int u = 0; u < 8; u++) {
            float4 bb = *reinterpret_cast<const float4*>(&b3[e0 + 4*u]);
            z2[2*u]   = pack2(bb.x, bb.y);
            z2[2*u+1] = pack2(bb.z, bb.w);
        }
#pragma unroll 4
        for (int ci = 0; ci < 128; ci++) {
            float hv = h2s[px*132 + ci];
            u64 s = splat2(hv);
#pragma unroll
            for (int u = 0; u < 8; u++) {
                float4 wv = *reinterpret_cast<const float4*>(&w3[ci*EMB + e0 + 4*u]);
                ffma2(z2[2*u],   s, pack2(wv.x, wv.y));
                ffma2(z2[2*u+1], s, pack2(wv.z, wv.w));
            }
        }
        float* dst = &g_ze[((n*H2v+oy)*W2v + px)*EMB + e0];
#pragma unroll
        for (int u = 0; u < 8; u++) {
            float f0,f1,f2,f3;
            unpack2(z2[2*u], f0, f1); unpack2(z2[2*u+1], f2, f3);
            *reinterpret_cast<float4*>(dst + 4*u) = make_float4(f0, f1, f2, f3);
        }
    }
}

// ================= VQ: argmin over 1024 codes, tok + z_st + loss =================
#define CSTR 68
__global__ void k_vq(const float* __restrict__ cb, float* __restrict__ dout) {
    __shared__ float cs[64*CSTR];
    __shared__ float e2s[64];
    __shared__ float bval[128];
    __shared__ int   bidx[128];
    __shared__ int   widx[16];
    __shared__ float lred[128];
    int tid = threadIdx.x;
    int pb = blockIdx.x * 16;
    int p = tid & 15;
    int g = tid >> 4;   // 0..7
    float4 z4[16];
    const float* zp = &g_ze[(pb + p)*EMB];
#pragma unroll
    for (int i = 0; i < 16; i++) z4[i] = *reinterpret_cast<const float4*>(&zp[4*i]);
    float best = 3.4e38f; int bi = 0;
    for (int ch = 0; ch < 16; ch++) {
        for (int i = tid; i < 64*16; i += 128) {
            int cj = i >> 4; int d4 = i & 15;
            float4 v = *reinterpret_cast<const float4*>(&cb[(ch*64+cj)*EMB + 4*d4]);
            *reinterpret_cast<float4*>(&cs[cj*CSTR + 4*d4]) = v;
        }
        __syncthreads();
        if (tid < 64) {
            float s = 0.0f;
#pragma unroll 8
            for (int d = 0; d < 64; d++) { float c = cs[tid*CSTR + d]; s = fmaf(c, c, s); }
            e2s[tid] = s;
        }
        __syncthreads();
#pragma unroll
        for (int j = 0; j < 8; j++) {
            int cj = g*8 + j;
            const float* cp = &cs[cj*CSTR];
            float dot = 0.0f;
#pragma unroll
            for (int i = 0; i < 16; i++) {
                float4 c = *reinterpret_cast<const float4*>(&cp[4*i]);
                dot = fmaf(z4[i].x, c.x, dot); dot = fmaf(z4[i].y, c.y, dot);
                dot = fmaf(z4[i].z, c.z, dot); dot = fmaf(z4[i].w, c.w, dot);
            }
            float dist = e2s[cj] - 2.0f*dot;
            int gidx = ch*64 + cj;
            if (dist < best || (dist == best && gidx < bi)) { best = dist; bi = gidx; }
        }
        __syncthreads();
    }
    bval[tid] = best; bidx[tid] = bi;
    __syncthreads();
    if (tid < 16) {
        float bb = bval[tid]; int bbi = bidx[tid];
        for (int k = 1; k < 8; k++) {
            float v = bval[tid + 16*k]; int vi = bidx[tid + 16*k];
            if (v < bb || (v == bb && vi < bbi)) { bb = v; bbi = vi; }
        }
        widx[tid] = bbi;
        dout[TOK_OFF + pb + tid] = (float)bbi;
    }
    __syncthreads();
    int idx = widx[p];
    float lsum = 0.0f;
    const float* cq = &cb[idx*EMB + g*8];
    const float* ze = &g_ze[(pb + p)*EMB + g*8];
    float*       zs = &g_zst[(pb + p)*EMB + g*8];
#pragma unroll
    for (int d = 0; d < 8; d++) {
        float zq = cq[d]; float z = ze[d];
        float diff = zq - z;
        zs[d] = z + diff;
        lsum = fmaf(diff, diff, lsum);
    }
    lred[tid] = lsum;
    __syncthreads();
    for (int s = 64; s > 0; s >>= 1) {
        if (tid < s) lred[tid] += lred[tid + s];
        __syncthreads();
    }
    if (tid == 0) atomicAdd(&g_loss, lred[0]);
}

// ================= convt1 (GEMM-tiled, f32x2): z_st -> g1 (gelu) =================
// block = 256 threads. tile: 128 ox (one row) x 128 co. grid (128 oy, 16 n).
__global__ void __launch_bounds__(256) k_convt1(const float* __restrict__ w, const float* __restrict__ b) {
    __shared__ float ins[1072];   // [kyi][cik][67] (66 used)
    __shared__ float Bs[8192];    // [(kyi*4+kx)*8+cik][128]
    int tid = threadIdx.x;
    int oy = blockIdx.x, n = blockIdx.y;
    int pgx = tid & 15, cg = tid >> 4;
    int par = pgx >> 3, pa = pgx & 7;
    int co0 = cg * 8;
    int kyA = oy & 1;
    int iy0 = (oy + kyA - 2) >> 1;
    u64 acc2[8][4];
    {
        float4 b0 = *reinterpret_cast<const float4*>(&b[co0]);
        float4 b1 = *reinterpret_cast<const float4*>(&b[co0+4]);
        u64 p0 = pack2(b0.x,b0.y), p1 = pack2(b0.z,b0.w);
        u64 p2 = pack2(b1.x,b1.y), p3 = pack2(b1.z,b1.w);
#pragma unroll
        for (int j = 0; j < 8; j++) { acc2[j][0]=p0; acc2[j][1]=p1; acc2[j][2]=p2; acc2[j][3]=p3; }
    }
    int abase = 4*pa + par;
#pragma unroll 1
    for (int ch = 0; ch < 8; ch++) {
        int ci0 = ch * 8;
        for (int i = tid; i < 264; i += 256) {
            int kyi = i / 132; int r = i - kyi*132; int ixl = r >> 1; int f4 = r & 1;
            int iy = iy0 + kyi; int ix = ixl - 1;
            float4 v = make_float4(0,0,0,0);
            if (iy >= 0 && iy < H2v && ix >= 0 && ix < W2v)
                v = *reinterpret_cast<const float4*>(&g_zst[((n*H2v+iy)*W2v+ix)*EMB + ci0 + 4*f4]);
            float* dst = &ins[(kyi*8 + 4*f4)*67 + ixl];
            dst[0] = v.x; dst[67] = v.y; dst[134] = v.z; dst[201] = v.w;
        }
        for (int i = tid; i < 2048; i += 256) {
            int co4 = i & 31; int cik = (i >> 5) & 7; int kx = (i >> 8) & 3; int kyi = i >> 10;
            int ky = kyA + 2*kyi;
            float4 wv = *reinterpret_cast<const float4*>(&w[(((ky*4+kx)*EMB) + ci0 + cik)*HID + co4*4]);
            *reinterpret_cast<float4*>(&Bs[((kyi*4+kx)*8+cik)*128 + co4*4]) = wv;
        }
        __syncthreads();
#pragma unroll
        for (int cik = 0; cik < 8; cik++) {
#pragma unroll
            for (int kyi = 0; kyi < 2; kyi++) {
#pragma unroll
                for (int kxi = 0; kxi < 2; kxi++) {
                    int kx = par + 2*kxi;
                    const u64* bp = reinterpret_cast<const u64*>(&Bs[((kyi*4+kx)*8+cik)*128 + co0]);
                    u64 w01 = bp[0], w23 = bp[1], w45 = bp[2], w67 = bp[3];
                    const float* ap = &ins[(kyi*8+cik)*67 + abase + kxi];
                    float a0 = ap[0],  a1 = ap[1],  a2 = ap[2],  a3 = ap[3];
                    float a4 = ap[32], a5 = ap[33], a6 = ap[34], a7 = ap[35];
                    FFMA2_8(0,a0) FFMA2_8(1,a1) FFMA2_8(2,a2) FFMA2_8(3,a3)
                    FFMA2_8(4,a4) FFMA2_8(5,a5) FFMA2_8(6,a6) FFMA2_8(7,a7)
                }
            }
        }
        __syncthreads();
    }
#pragma unroll
    for (int j = 0; j < 8; j++) {
        int mxl = (j < 4) ? (4*pa + j) : (32 + 4*pa + j - 4);
        int ox = 2*mxl + par;
        float f0,f1,f2,f3,f4,f5,f6,f7;
        unpack2(acc2[j][0], f0, f1); unpack2(acc2[j][1], f2, f3);
        unpack2(acc2[j][2], f4, f5); unpack2(acc2[j][3], f6, f7);
        float4 o0 = make_float4(gelu_f(f0), gelu_f(f1), gelu_f(f2), gelu_f(f3));
        float4 o1 = make_float4(gelu_f(f4), gelu_f(f5), gelu_f(f6), gelu_f(f7));
        float* dst = &g_g1[((n*H1v+oy)*W1v + ox)*HID + co0];
        *reinterpret_cast<float4*>(dst)     = o0;
        *reinterpret_cast<float4*>(dst + 4) = o1;
    }
}

// ================= convt2 (GEMM-tiled, f32x2) + gelu + 1x1(128->3): g1 -> x_rec =================
// block = 256 threads. tile: 128 ox x 128 co. grid (2 bx, 256 oy, 16 n). dyn smem.
__global__ void __launch_bounds__(256) k_convt2(const float* __restrict__ w, const float* __restrict__ b,
                                                const float* __restrict__ w3, const float* __restrict__ b3,
                                                float* __restrict__ dout) {
    extern __shared__ float sm[];
    float* ins = sm;            // 1072: [kyi][cik][67]
    float* Bs  = sm + 1072;     // 8192
    float* gs  = sm;            // reused: [128 px][132]
    int tid = threadIdx.x;
    int bx = blockIdx.x, oy = blockIdx.y, n = blockIdx.z;
    int x0 = bx * 128, xb = bx * 64;
    int pgx = tid & 15, cg = tid >> 4;
    int par = pgx >> 3, pa = pgx & 7;
    int co0 = cg * 8;
    int kyA = oy & 1;
    int iy0 = (oy + kyA - 2) >> 1;
    u64 acc2[8][4];
    {
        float4 b0 = *reinterpret_cast<const float4*>(&b[co0]);
        float4 b1 = *reinterpret_cast<const float4*>(&b[co0+4]);
        u64 p0 = pack2(b0.x,b0.y), p1 = pack2(b0.z,b0.w);
        u64 p2 = pack2(b1.x,b1.y), p3 = pack2(b1.z,b1.w);
#pragma unroll
        for (int j = 0; j < 8; j++) { acc2[j][0]=p0; acc2[j][1]=p1; acc2[j][2]=p2; acc2[j][3]=p3; }
    }
    int abase = 4*pa + par;
#pragma unroll 1
    for (int ch = 0; ch < 16; ch++) {
        int ci0 = ch * 8;
        for (int i = tid; i < 264; i += 256) {
            int kyi = i / 132; int r = i - kyi*132; int ixl = r >> 1; int f4 = r & 1;
            int iy = iy0 + kyi; int ix = xb + ixl - 1;
            float4 v = make_float4(0,0,0,0);
            if (iy >= 0 && iy < H1v && ix >= 0 && ix < W1v)
                v = *reinterpret_cast<const float4*>(&g_g1[((n*H1v+iy)*W1v+ix)*HID + ci0 + 4*f4]);
            float* dst = &ins[(kyi*8 + 4*f4)*67 + ixl];
            dst[0] = v.x; dst[67] = v.y; dst[134] = v.z; dst[201] = v.w;
        }
        for (int i = tid; i < 2048; i += 256) {
            int co4 = i & 31; int cik = (i >> 5) & 7; int kx = (i >> 8) & 3; int kyi = i >> 10;
            int ky = kyA + 2*kyi;
            float4 wv = *reinterpret_cast<const float4*>(&w[(((ky*4+kx)*HID) + ci0 + cik)*HID + co4*4]);
            *reinterpret_cast<float4*>(&Bs[((kyi*4+kx)*8+cik)*128 + co4*4]) = wv;
        }
        __syncthreads();
#pragma unroll
        for (int cik = 0; cik < 8; cik++) {
#pragma unroll
            for (int kyi = 0; kyi < 2; kyi++) {
#pragma unroll
                for (int kxi = 0; kxi < 2; kxi++) {
                    int kx = par + 2*kxi;
                    const u64* bp = reinterpret_cast<const u64*>(&Bs[((kyi*4+kx)*8+cik)*128 + co0]);
                    u64 w01 = bp[0], w23 = bp[1], w45 = bp[2], w67 = bp[3];
                    const float* ap = &ins[(kyi*8+cik)*67 + abase + kxi];
                    float a0 = ap[0],  a1 = ap[1],  a2 = ap[2],  a3 = ap[3];
                    float a4 = ap[32], a5 = ap[33], a6 = ap[34], a7 = ap[35];
                    FFMA2_8(0,a0) FFMA2_8(1,a1) FFMA2_8(2,a2) FFMA2_8(3,a3)
                    FFMA2_8(4,a4) FFMA2_8(5,a5) FFMA2_8(6,a6) FFMA2_8(7,a7)
                }
            }
        }
        __syncthreads();
    }
    // gelu -> gs [128 px][132]
#pragma unroll
    for (int j = 0; j < 8; j++) {
        int mxl = (j < 4) ? (4*pa + j) : (32 + 4*pa + j - 4);
        int ox = 2*mxl + par;
        float f0,f1,f2,f3,f4,f5,f6,f7;
        unpack2(acc2[j][0], f0, f1); unpack2(acc2[j][1], f2, f3);
        unpack2(acc2[j][2], f4, f5); unpack2(acc2[j][3], f6, f7);
        float4 o0 = make_float4(gelu_f(f0), gelu_f(f1), gelu_f(f2), gelu_f(f3));
        float4 o1 = make_float4(gelu_f(f4), gelu_f(f5), gelu_f(f6), gelu_f(f7));
        *reinterpret_cast<float4*>(&gs[ox*132 + co0])     = o0;
        *reinterpret_cast<float4*>(&gs[ox*132 + co0 + 4]) = o1;
    }
    __syncthreads();
    // fused 1x1: 128 -> 3. 2 threads per px, shfl combine.
    {
        int px = tid >> 1;
        int half = tid & 1;
        float p0 = 0.0f, p1 = 0.0f, p2 = 0.0f;
        const float* gp = &gs[px*132 + half*64];
        const float* wp = &w3[half*64*3];
#pragma unroll 8
        for (int k = 0; k < 64; k++) {
            float gv = gp[k];
            p0 = fmaf(gv, wp[3*k+0], p0);
            p1 = fmaf(gv, wp[3*k+1], p1);
            p2 = fmaf(gv, wp[3*k+2], p2);
        }
        p0 += __shfl_xor_sync(0xffffffffu, p0, 1);
        p1 += __shfl_xor_sync(0xffffffffu, p1, 1);
        p2 += __shfl_xor_sync(0xffffffffu, p2, 1);
        if (half == 0) {
            float* dst = &dout[((n*H0+oy)*W0 + x0 + px)*3];
            dst[0] = p0 + b3[0];
            dst[1] = p1 + b3[1];
            dst[2] = p2 + b3[2];
        }
    }
}

// ================= finalize losses =================
__global__ void k_final(float* __restrict__ dout) {
    float l = g_loss / (float)(TOK_ELEMS * EMB);
    dout[LOSS_OFF]     = l;
    dout[LOSS_OFF + 1] = l;
}

// ================= launch =================
extern "C" void kernel_launch(void* const* d_in, const int* in_sizes, int n_in,
                              void* d_out, int out_size) {
    const float* x      = (const float*)d_in[0];
    const float* enc_w1 = (const float*)d_in[1];
    const float* enc_b1 = (const float*)d_in[2];
    const float* enc_w2 = (const float*)d_in[3];
    const float* enc_b2 = (const float*)d_in[4];
    const float* enc_w3 = (const float*)d_in[5];
    const float* enc_b3 = (const float*)d_in[6];
    const float* cb     = (const float*)d_in[7];
    const float* dec_w1 = (const float*)d_in[8];
    const float* dec_b1 = (const float*)d_in[9];
    const float* dec_w2 = (const float*)d_in[10];
    const float* dec_b2 = (const float*)d_in[11];
    const float* dec_w3 = (const float*)d_in[12];
    const float* dec_b3 = (const float*)d_in[13];
    float* out = (float*)d_out;

    static int smem_set = 0;
    const int smem_t2 = 128*132*4;   // gs [128][132] = 67584 B
    if (!smem_set) {
        cudaFuncSetAttribute(k_convt2, cudaFuncAttributeMaxDynamicSharedMemorySize, smem_t2);
        smem_set = 1;
    }

    k_conv1<<<dim3(8, 128, 16), 128>>>(x, enc_w1, enc_b1);
    k_conv2<<<dim3(64, 16), 128>>>(enc_w2, enc_b2, enc_w3, enc_b3);
    k_vq<<<4096, 128>>>(cb, out);
    k_convt1<<<dim3(128, 16), 256>>>(dec_w1, dec_b1);
    k_convt2<<<dim3(2, 256, 16), 256, smem_t2>>>(dec_w2, dec_b2, dec_w3, dec_b3, out);
    k_final<<<1, 1>>>(out);
}